// round 1
// baseline (speedup 1.0000x reference)
#include <cuda_runtime.h>

// PairWiseRankingLoss, closed form.
// gama=1 and p=sigmoid(x) in (0,1)  =>  1 + p_i - p_j > 0 always, relu is identity
// on the masked set. So per row:
//   loss_b = n0*n1*1 + n1*sum_{y=0} p - n0*sum_{y=1} p
// Total = sum_b loss_b. One pass over [128,1024] inputs.

#define B_ROWS 128
#define L_COLS 1024
#define NTHREADS 256   // 256 threads * 4 elems (float4) = 1024 = one row per block

__device__ float g_partials[B_ROWS];
__device__ unsigned int g_ticket;   // zero-initialized at module load; reset by last block

__global__ void __launch_bounds__(NTHREADS)
prl_kernel(const float* __restrict__ logit,
           const int*   __restrict__ y,
           float*       __restrict__ out)
{
    const int b = blockIdx.x;
    const int t = threadIdx.x;

    // Vectorized coalesced loads: 4 consecutive elements per thread.
    const float4 lv = reinterpret_cast<const float4*>(logit + b * L_COLS)[t];
    const int4   yv = reinterpret_cast<const int4*>(y + b * L_COLS)[t];

    float sum_neg = 0.f, sum_pos = 0.f;
    int   cnt1 = 0;

    {
        float p;
        p = 1.f / (1.f + __expf(-lv.x)); if (yv.x) { sum_pos += p; cnt1++; } else sum_neg += p;
        p = 1.f / (1.f + __expf(-lv.y)); if (yv.y) { sum_pos += p; cnt1++; } else sum_neg += p;
        p = 1.f / (1.f + __expf(-lv.z)); if (yv.z) { sum_pos += p; cnt1++; } else sum_neg += p;
        p = 1.f / (1.f + __expf(-lv.w)); if (yv.w) { sum_pos += p; cnt1++; } else sum_neg += p;
    }

    // Warp reduction (3 quantities).
    #pragma unroll
    for (int off = 16; off > 0; off >>= 1) {
        sum_neg += __shfl_down_sync(0xffffffffu, sum_neg, off);
        sum_pos += __shfl_down_sync(0xffffffffu, sum_pos, off);
        cnt1    += __shfl_down_sync(0xffffffffu, cnt1,    off);
    }

    __shared__ float s_neg[8], s_pos[8];
    __shared__ int   s_cnt[8];
    const int wid = t >> 5, lid = t & 31;
    if (lid == 0) { s_neg[wid] = sum_neg; s_pos[wid] = sum_pos; s_cnt[wid] = cnt1; }
    __syncthreads();

    if (wid == 0) {
        sum_neg = (lid < 8) ? s_neg[lid] : 0.f;
        sum_pos = (lid < 8) ? s_pos[lid] : 0.f;
        cnt1    = (lid < 8) ? s_cnt[lid] : 0;
        #pragma unroll
        for (int off = 4; off > 0; off >>= 1) {
            sum_neg += __shfl_down_sync(0xffffffffu, sum_neg, off);
            sum_pos += __shfl_down_sync(0xffffffffu, sum_pos, off);
            cnt1    += __shfl_down_sync(0xffffffffu, cnt1,    off);
        }
        if (lid == 0) {
            const float c1 = (float)cnt1;
            const float c0 = (float)(L_COLS - cnt1);
            // row loss = c0*c1*gama + c1*sum_neg - c0*sum_pos   (gama = 1)
            g_partials[b] = c0 * c1 + c1 * sum_neg - c0 * sum_pos;

            __threadfence();
            const unsigned int ticket = atomicAdd(&g_ticket, 1u);
            if (ticket == B_ROWS - 1) {
                // Last block to finish: reduce 128 partials, write scalar out,
                // reset ticket for the next (graph-replayed) launch.
                __threadfence();
                double tot = 0.0;
                #pragma unroll 8
                for (int i = 0; i < B_ROWS; i++) tot += (double)g_partials[i];
                *out = (float)tot;
                g_ticket = 0u;
            }
        }
    }
}

extern "C" void kernel_launch(void* const* d_in, const int* in_sizes, int n_in,
                              void* d_out, int out_size)
{
    const float* logit = (const float*)d_in[0];
    const int*   y     = (const int*)d_in[1];
    float*       out   = (float*)d_out;
    (void)in_sizes; (void)n_in; (void)out_size;

    prl_kernel<<<B_ROWS, NTHREADS>>>(logit, y, out);
}

// round 2
// speedup vs baseline: 2.8986x; 2.8986x over previous
#include <cuda_runtime.h>

// PairWiseRankingLoss, closed form.
// gama=1 and p=sigmoid(x) in (0,1)  =>  1 + p_i - p_j > 0 for every pair, so the
// relu never clips and the masked pair-sum factorizes per row:
//   loss_b = n0*n1*gama + n1*sum_{y=0} p - n0*sum_{y=1} p
// Total = sum_b loss_b. One pass over the [128,1024] inputs, single kernel,
// last-finisher block does a PARALLEL fp32 reduction of the 128 row partials.

#define B_ROWS 128
#define L_COLS 1024
#define NTHREADS 256   // 256 threads * 4 elems (float4) = 1024 = one row per block

__device__ float g_partials[B_ROWS];
__device__ unsigned int g_ticket;   // zero at module load; last block resets it each launch

__global__ void __launch_bounds__(NTHREADS)
prl_kernel(const float* __restrict__ logit,
           const int*   __restrict__ y,
           float*       __restrict__ out)
{
    const int b = blockIdx.x;
    const int t = threadIdx.x;
    const int wid = t >> 5, lid = t & 31;

    // Vectorized coalesced loads: 4 consecutive elements per thread.
    const float4 lv = reinterpret_cast<const float4*>(logit + b * L_COLS)[t];
    const int4   yv = reinterpret_cast<const int4*>(y + b * L_COLS)[t];

    // Branchless: sum_all = sum p, sum_pos = sum y*p, cnt1 = sum y.
    float sum_all = 0.f, sum_pos = 0.f;
    int   cnt1 = 0;
    {
        float p;
        p = 1.f / (1.f + __expf(-lv.x)); sum_all += p; sum_pos = fmaf((float)yv.x, p, sum_pos); cnt1 += yv.x;
        p = 1.f / (1.f + __expf(-lv.y)); sum_all += p; sum_pos = fmaf((float)yv.y, p, sum_pos); cnt1 += yv.y;
        p = 1.f / (1.f + __expf(-lv.z)); sum_all += p; sum_pos = fmaf((float)yv.z, p, sum_pos); cnt1 += yv.z;
        p = 1.f / (1.f + __expf(-lv.w)); sum_all += p; sum_pos = fmaf((float)yv.w, p, sum_pos); cnt1 += yv.w;
    }

    // Warp reduction (3 quantities).
    #pragma unroll
    for (int off = 16; off > 0; off >>= 1) {
        sum_all += __shfl_down_sync(0xffffffffu, sum_all, off);
        sum_pos += __shfl_down_sync(0xffffffffu, sum_pos, off);
        cnt1    += __shfl_down_sync(0xffffffffu, cnt1,    off);
    }

    __shared__ float s_a[8], s_p[8];
    __shared__ int   s_c[8];
    __shared__ int   s_is_last;
    if (lid == 0) { s_a[wid] = sum_all; s_p[wid] = sum_pos; s_c[wid] = cnt1; }
    __syncthreads();

    if (t == 0) {
        float a = 0.f, pp = 0.f; int c = 0;
        #pragma unroll
        for (int i = 0; i < 8; i++) { a += s_a[i]; pp += s_p[i]; c += s_c[i]; }
        const float c1 = (float)c;
        const float c0 = (float)(L_COLS - c);
        const float sneg = a - pp;
        // row loss = c0*c1*gama + c1*sum_neg - c0*sum_pos   (gama = 1)
        g_partials[b] = c0 * c1 + c1 * sneg - c0 * pp;

        __threadfence();
        const unsigned int ticket = atomicAdd(&g_ticket, 1u);
        s_is_last = (ticket == B_ROWS - 1);
    }
    __syncthreads();

    // Last block to finish: ALL threads cooperate on the 128 -> 1 reduction.
    if (s_is_last) {
        __threadfence();  // acquire: see every block's g_partials store
        float v = (t < B_ROWS) ? __ldcg(&g_partials[t]) : 0.f;
        #pragma unroll
        for (int off = 16; off > 0; off >>= 1)
            v += __shfl_down_sync(0xffffffffu, v, off);
        if (lid == 0) s_a[wid] = v;
        __syncthreads();
        if (t == 0) {
            float tot = 0.f;
            #pragma unroll
            for (int i = 0; i < 8; i++) tot += s_a[i];
            *out = tot;
            g_ticket = 0u;   // rearm for next graph replay
        }
    }
}

extern "C" void kernel_launch(void* const* d_in, const int* in_sizes, int n_in,
                              void* d_out, int out_size)
{
    const float* logit = (const float*)d_in[0];
    const int*   y     = (const int*)d_in[1];
    float*       out   = (float*)d_out;
    (void)in_sizes; (void)n_in; (void)out_size;

    prl_kernel<<<B_ROWS, NTHREADS>>>(logit, y, out);
}